// round 15
// baseline (speedup 1.0000x reference)
#include <cuda_runtime.h>
#include <cuda_fp16.h>
#include <stdint.h>

// Problem constants
#define BB 32
#define TT 2000
#define HH 768
#define SS 100
#define NVV 100
#define BSROWS 3200            // B*S
#define ROWSTRIDE 2100         // NV + T
#define K2 1536                // 2*H

// Block-range layout of mega_kernel (agg blocks handle FOUR segments each)
#define NBLK_AGG  (BSROWS / 4)           // 800
#define NBLK_VIS  (BB * 4)               // 128
#define NBLK_WC   384                    // 384 * 384 f4 = H*H/4
#define NBLK_MEGA (NBLK_AGG + NBLK_VIS + NBLK_WC)   // 1312 (single wave)

// ---------------------------------------------------------------------------
// Scratch (device globals; allocation forbidden)
// ---------------------------------------------------------------------------
__device__ unsigned short g_af[BSROWS * HH];    // fp16 segment means (A)
__device__ unsigned short g_wf[HH * HH];        // fp16 W1 (w[:, :768])
__device__ float g_vispart[BB * 4 * HH];        // partial sums of vision rows
__device__ float g_v2[BB * HH];                 // vision @ W2^T + bias

// ---------------------------------------------------------------------------
// Helpers
// ---------------------------------------------------------------------------
__device__ __forceinline__ uint32_t smem_u32(const void* p) {
    uint32_t a;
    asm("{ .reg .u64 t; cvta.to.shared.u64 t, %1; cvt.u32.u64 %0, t; }" : "=r"(a) : "l"(p));
    return a;
}
__device__ __forceinline__ void cpasync16(uint32_t saddr, const void* g) {
    asm volatile("cp.async.cg.shared.global [%0], [%1], 16;" :: "r"(saddr), "l"(g));
}
#define CP_COMMIT() asm volatile("cp.async.commit_group;" ::: "memory")

__device__ __forceinline__ void ldsm_x4(uint32_t* r, uint32_t addr) {
    asm volatile("ldmatrix.sync.aligned.m8n8.x4.shared.b16 {%0,%1,%2,%3}, [%4];"
                 : "=r"(r[0]), "=r"(r[1]), "=r"(r[2]), "=r"(r[3]) : "r"(addr));
}
__device__ __forceinline__ void ldsm_x2(uint32_t* r, uint32_t addr) {
    asm volatile("ldmatrix.sync.aligned.m8n8.x2.shared.b16 {%0,%1}, [%2];"
                 : "=r"(r[0]), "=r"(r[1]) : "r"(addr));
}
__device__ __forceinline__ void mma_f16(float* c, const uint32_t* a, const uint32_t* b) {
    asm volatile("mma.sync.aligned.m16n8k16.row.col.f32.f16.f16.f32 "
                 "{%0,%1,%2,%3}, {%4,%5,%6,%7}, {%8,%9}, {%0,%1,%2,%3};"
                 : "+f"(c[0]), "+f"(c[1]), "+f"(c[2]), "+f"(c[3])
                 : "r"(a[0]), "r"(a[1]), "r"(a[2]), "r"(a[3]), "r"(b[0]), "r"(b[1]));
}

// pack 4 floats -> 4 fp16 in a uint2
__device__ __forceinline__ uint2 pack4h(float4 v) {
    __half2 p01 = __floats2half2_rn(v.x, v.y);
    __half2 p23 = __floats2half2_rn(v.z, v.w);
    uint2 u;
    u.x = *reinterpret_cast<uint32_t*>(&p01);
    u.y = *reinterpret_cast<uint32_t*>(&p23);
    return u;
}

// accumulate a segment's rows (list in smem) into a float4 and store fp16 mean
__device__ __forceinline__ void seg_accum_store(const float* __restrict__ base,
                                                const unsigned short* __restrict__ list,
                                                int cnt, int h4, size_t orow) {
    float inv = (cnt > 0) ? (1.0f / (float)cnt) : 0.0f;
    float4 acc = make_float4(0.f, 0.f, 0.f, 0.f);
    int i = 0;
    for (; i + 8 <= cnt; i += 8) {
        float4 v[8];
        #pragma unroll
        for (int j = 0; j < 8; j++)
            v[j] = *(const float4*)&base[(size_t)list[i + j] * HH + h4 * 4];
        #pragma unroll
        for (int j = 0; j < 8; j++) {
            acc.x += v[j].x; acc.y += v[j].y; acc.z += v[j].z; acc.w += v[j].w;
        }
    }
    for (; i + 4 <= cnt; i += 4) {
        float4 v[4];
        #pragma unroll
        for (int j = 0; j < 4; j++)
            v[j] = *(const float4*)&base[(size_t)list[i + j] * HH + h4 * 4];
        #pragma unroll
        for (int j = 0; j < 4; j++) {
            acc.x += v[j].x; acc.y += v[j].y; acc.z += v[j].z; acc.w += v[j].w;
        }
    }
    for (; i < cnt; i++) {
        float4 v = *(const float4*)&base[(size_t)list[i] * HH + h4 * 4];
        acc.x += v.x; acc.y += v.y; acc.z += v.z; acc.w += v.w;
    }
    acc.x *= inv; acc.y *= inv; acc.z *= inv; acc.w *= inv;
    *(uint2*)&g_af[orow * HH + h4 * 4] = pack4h(acc);
}

// ---------------------------------------------------------------------------
// Mega kernel: block-range specialization fuses agg (4 segments per block) /
// vision partials / W1 fp16 convert so they overlap on-chip. 192 threads.
// Grid 1312 blocks <= single-wave capacity: everything resident at once.
// ---------------------------------------------------------------------------
__global__ __launch_bounds__(192) void mega_kernel(const float* __restrict__ feat,
                                                   const int* __restrict__ mask,
                                                   const float* __restrict__ w) {
    const int blk = blockIdx.x;

    if (blk < NBLK_AGG) {
        // ---- segment means -> fp16. One block per (b, segment-quad). ----
        int b = blk / (SS / 4);
        int s0 = (blk % (SS / 4)) * 4;          // segments s0..s0+3

        __shared__ unsigned short lists[4][TT];  // 16 KB
        __shared__ int cnts[4];
        if (threadIdx.x < 4) cnts[threadIdx.x] = 0;
        __syncthreads();

        const int* mrow = mask + (size_t)b * TT;
        for (int t = threadIdx.x; t < TT; t += 192) {
            int m = mrow[t] - 1 - s0;           // 0..3 if in this quad
            if ((unsigned)m < 4u) {
                int pos = atomicAdd(&cnts[m], 1);
                lists[m][pos] = (unsigned short)t;
            }
        }
        __syncthreads();

        const float* base = feat + ((size_t)b * ROWSTRIDE + NVV) * HH;
        int h4 = threadIdx.x;                   // 0..191
        size_t row0 = (size_t)b * SS + s0;
        #pragma unroll
        for (int q = 0; q < 4; q++)
            seg_accum_store(base, lists[q], cnts[q], h4, row0 + q);

    } else if (blk < NBLK_AGG + NBLK_VIS) {
        // ---- vision partial sums: 25 rows per block ----
        int idx = blk - NBLK_AGG;
        int b = idx >> 2, part = idx & 3;
        const float* base = feat + ((size_t)b * ROWSTRIDE + part * 25) * HH;
        int h4 = threadIdx.x;
        float4 acc = make_float4(0.f, 0.f, 0.f, 0.f);
        int r = 0;
        for (; r + 4 <= 25; r += 4) {
            float4 v0 = *(const float4*)&base[(size_t)(r + 0) * HH + h4 * 4];
            float4 v1 = *(const float4*)&base[(size_t)(r + 1) * HH + h4 * 4];
            float4 v2 = *(const float4*)&base[(size_t)(r + 2) * HH + h4 * 4];
            float4 v3 = *(const float4*)&base[(size_t)(r + 3) * HH + h4 * 4];
            acc.x += v0.x + v1.x + v2.x + v3.x;
            acc.y += v0.y + v1.y + v2.y + v3.y;
            acc.z += v0.z + v1.z + v2.z + v3.z;
            acc.w += v0.w + v1.w + v2.w + v3.w;
        }
        for (; r < 25; r++) {
            float4 v = *(const float4*)&base[(size_t)r * HH + h4 * 4];
            acc.x += v.x; acc.y += v.y; acc.z += v.z; acc.w += v.w;
        }
        *(float4*)&g_vispart[(size_t)idx * HH + h4 * 4] = acc;

    } else {
        // ---- W1 -> fp16: 384 float4s per block (2 per thread) ----
        int wblk = blk - (NBLK_AGG + NBLK_VIS);
        int i0 = wblk * 384 + threadIdx.x;
        #pragma unroll
        for (int j = 0; j < 2; j++) {
            int idx = i0 + j * 192;
            int n = idx / (HH / 4);
            int k4 = idx % (HH / 4);
            float4 v = *(const float4*)&w[(size_t)n * K2 + k4 * 4];
            *(uint2*)&g_wf[(size_t)n * HH + k4 * 4] = pack4h(v);
        }
    }
}

// ---------------------------------------------------------------------------
// Kernel: g_v2[b][n] = vision_mean[b] . W2[n] + bias[n].
// Warp-per-n, 4 batches per warp; vision mean computed inline from partials.
// grid (96, 8), 256 threads. Full fp32 (exact).
// ---------------------------------------------------------------------------
__global__ __launch_bounds__(256) void v2_kernel(const float* __restrict__ w,
                                                 const float* __restrict__ bias) {
    const int lane = threadIdx.x & 31;
    const int wid = threadIdx.x >> 5;
    const int n = blockIdx.x * 8 + wid;         // 0..767
    const int b0 = blockIdx.y * 4;              // 0,4,...,28
    const float invN = 1.0f / (float)NVV;

    const float* wr = w + (size_t)n * K2 + HH;  // W2 row n
    float a0 = 0.f, a1 = 0.f, a2 = 0.f, a3 = 0.f;
    #pragma unroll
    for (int i = 0; i < 6; i++) {
        int k4 = i * 32 + lane;                 // float4 index, coalesced
        float4 wv = *(const float4*)&wr[k4 * 4];
        #pragma unroll
        for (int bb = 0; bb < 4; bb++) {
            const float* pp = &g_vispart[(size_t)((b0 + bb) * 4) * HH + k4 * 4];
            float4 p0 = *(const float4*)(pp);
            float4 p1 = *(const float4*)(pp + HH);
            float4 p2 = *(const float4*)(pp + 2 * HH);
            float4 p3 = *(const float4*)(pp + 3 * HH);
            float sx = (p0.x + p1.x + p2.x + p3.x) * invN;
            float sy = (p0.y + p1.y + p2.y + p3.y) * invN;
            float sz = (p0.z + p1.z + p2.z + p3.z) * invN;
            float sw = (p0.w + p1.w + p2.w + p3.w) * invN;
            float d = sx * wv.x + sy * wv.y + sz * wv.z + sw * wv.w;
            if (bb == 0) a0 += d;
            else if (bb == 1) a1 += d;
            else if (bb == 2) a2 += d;
            else a3 += d;
        }
    }
    #pragma unroll
    for (int off = 16; off; off >>= 1) {
        a0 += __shfl_xor_sync(0xFFFFFFFFu, a0, off);
        a1 += __shfl_xor_sync(0xFFFFFFFFu, a1, off);
        a2 += __shfl_xor_sync(0xFFFFFFFFu, a2, off);
        a3 += __shfl_xor_sync(0xFFFFFFFFu, a3, off);
    }
    if (lane == 0) {
        float bb = bias[n];
        g_v2[(size_t)(b0 + 0) * HH + n] = a0 + bb;
        g_v2[(size_t)(b0 + 1) * HH + n] = a1 + bb;
        g_v2[(size_t)(b0 + 2) * HH + n] = a2 + bb;
        g_v2[(size_t)(b0 + 3) * HH + n] = a3 + bb;
    }
}

// ---------------------------------------------------------------------------
// Kernel: mma.sync fp16 GEMM, 2 CTAs/SM for latency hiding.
// out[m][n] = sum_k A[m][k]*W1[n][k] + g_v2[m/S][n]   (both fp16, fp32 acc)
// BM=80, BN=128, BK=32, 24 stages, 4 smem buffers, grid (6,40)=240 CTAs
// (2/SM, still single wave). 8 warps 1(m)x8(n); warp tile 80x16.
// Per-warp work per k16: 5 ldsm_x4(A) + 2 ldsm_x2(B) + 10 MMAs.
// ---------------------------------------------------------------------------
#define BM 80
#define NSTG 24
#define NBUF 4
#define ROWH 40                       // padded row length in halfs (80 B)
#define STGA (BM * ROWH)              // A halfs per stage (3200)
#define STGB (128 * ROWH)             // B halfs per stage (5120)
#define GEMM_SMEM ((NBUF * STGA + NBUF * STGB) * 2)   // 66560 B

__global__ __launch_bounds__(256, 2) void gemm_kernel(float* __restrict__ out) {
    extern __shared__ unsigned short sm[];
    unsigned short* sA = sm;
    unsigned short* sB = sA + NBUF * STGA;

    const int tid = threadIdx.x;
    const int lane = tid & 31;
    const int wid = tid >> 5;
    const int wn = wid;               // 0..7 -> n offset wn*16
    const int n0 = blockIdx.x * 128;
    const int m0 = blockIdx.y * BM;

    const uint32_t bA = smem_u32(sA), bB = smem_u32(sB);

    float acc[5][2][4];
    #pragma unroll
    for (int i = 0; i < 5; i++)
        #pragma unroll
        for (int j = 0; j < 2; j++)
            #pragma unroll
            for (int r = 0; r < 4; r++) acc[i][j][r] = 0.f;

    auto issue_stage = [&](int s, int buf) {
        const int k0 = s * 32;
        // A: 80 rows x 4 chunks = 320 chunks of 16B
        {
            int idx = tid;                      // 0..255
            if (idx < BM * 4) {
                int row = idx >> 2;
                int c16 = idx & 3;
                uint32_t soff = (uint32_t)(buf * STGA + row * ROWH + c16 * 8) * 2u;
                cpasync16(bA + soff, &g_af[(size_t)(m0 + row) * HH + k0 + c16 * 8]);
            }
            idx = tid + 256;
            if (idx < BM * 4) {
                int row = idx >> 2;
                int c16 = idx & 3;
                uint32_t soff = (uint32_t)(buf * STGA + row * ROWH + c16 * 8) * 2u;
                cpasync16(bA + soff, &g_af[(size_t)(m0 + row) * HH + k0 + c16 * 8]);
            }
        }
        // B: 128 rows x 4 chunks = 512 chunks
        #pragma unroll
        for (int j = 0; j < 2; j++) {
            int idx = tid + j * 256;
            int row = idx >> 2;
            int c16 = idx & 3;
            uint32_t soff = (uint32_t)(buf * STGB + row * ROWH + c16 * 8) * 2u;
            cpasync16(bB + soff, &g_wf[(size_t)(n0 + row) * HH + k0 + c16 * 8]);
        }
        CP_COMMIT();
    };

    issue_stage(0, 0);
    issue_stage(1, 1);
    issue_stage(2, 2);

    for (int s = 0; s < NSTG; s++) {
        int rem = NSTG - 1 - s;
        if (rem >= 2)      asm volatile("cp.async.wait_group 2;" ::: "memory");
        else if (rem == 1) asm volatile("cp.async.wait_group 1;" ::: "memory");
        else               asm volatile("cp.async.wait_group 0;" ::: "memory");
        __syncthreads();

        if (s + 3 < NSTG) issue_stage(s + 3, (s + 3) % NBUF);

        const int buf = s % NBUF;
        const uint32_t stgA = (uint32_t)(buf * STGA) * 2u;
        const uint32_t stgB = (uint32_t)(buf * STGB) * 2u;

        #pragma unroll
        for (int ks = 0; ks < 2; ks++) {
            const int kh = ks * 16;
            uint32_t a[5][4], b[2][2];

            #pragma unroll
            for (int ti = 0; ti < 5; ti++) {
                int mr = ti * 16 + (lane & 15);
                uint32_t off = stgA + (uint32_t)(mr * ROWH + kh + (lane >> 4) * 8) * 2u;
                ldsm_x4(a[ti], bA + off);
            }
            #pragma unroll
            for (int tj = 0; tj < 2; tj++) {
                int nr = wn * 16 + tj * 8 + (lane & 7);
                uint32_t off = stgB + (uint32_t)(nr * ROWH + kh + ((lane >> 3) & 1) * 8) * 2u;
                ldsm_x2(b[tj], bB + off);
            }

            #pragma unroll
            for (int ti = 0; ti < 5; ti++)
                #pragma unroll
                for (int tj = 0; tj < 2; tj++)
                    mma_f16(acc[ti][tj], a[ti], b[tj]);
        }
    }
    __syncthreads();   // all warps done before smem reuse

    // Epilogue: fragments -> padded fp32 smem tile -> coalesced store + v2 add.
    float* st = (float*)sm;                     // 80 x 129 floats = 41280 B
    const int g = lane >> 2;
    const int t2 = (lane & 3) * 2;
    #pragma unroll
    for (int ti = 0; ti < 5; ti++)
        #pragma unroll
        for (int tj = 0; tj < 2; tj++) {
            int r0 = ti * 16 + g;
            int c0 = wn * 16 + tj * 8 + t2;
            st[r0 * 129 + c0]           = acc[ti][tj][0];
            st[r0 * 129 + c0 + 1]       = acc[ti][tj][1];
            st[(r0 + 8) * 129 + c0]     = acc[ti][tj][2];
            st[(r0 + 8) * 129 + c0 + 1] = acc[ti][tj][3];
        }
    __syncthreads();

    #pragma unroll 4
    for (int it = 0; it < BM * 128 / 256; it++) {
        int q = tid + it * 256;
        int row = q >> 7;
        int col = q & 127;
        int m = m0 + row;
        int b = m / SS;
        out[(size_t)m * HH + n0 + col] = st[row * 129 + col] + g_v2[(size_t)b * HH + n0 + col];
    }
}

// ---------------------------------------------------------------------------
extern "C" void kernel_launch(void* const* d_in, const int* in_sizes, int n_in,
                              void* d_out, int out_size) {
    const float* feat = (const float*)d_in[0];   // (B, NV+T, H) f32
    const int*   mask = (const int*)d_in[1];     // (B, T) i32
    const float* w    = (const float*)d_in[2];   // (H, 2H) f32
    const float* bias = (const float*)d_in[3];   // (H,) f32
    float* out = (float*)d_out;                  // (B, S, H) f32

    mega_kernel<<<NBLK_MEGA, 192>>>(feat, mask, w);
    v2_kernel<<<dim3(96, 8), 256>>>(w, bias);

    cudaFuncSetAttribute(gemm_kernel, cudaFuncAttributeMaxDynamicSharedMemorySize, GEMM_SMEM);
    gemm_kernel<<<dim3(HH / 128, BSROWS / BM), 256, GEMM_SMEM>>>(out);
}

// round 16
// speedup vs baseline: 1.0206x; 1.0206x over previous
#include <cuda_runtime.h>
#include <cuda_fp16.h>
#include <stdint.h>

// Problem constants
#define BB 32
#define TT 2000
#define HH 768
#define SS 100
#define NVV 100
#define BSROWS 3200            // B*S
#define ROWSTRIDE 2100         // NV + T
#define K2 1536                // 2*H

// Block-range layout of mega_kernel (agg blocks handle FOUR segments each)
#define NBLK_AGG  (BSROWS / 4)           // 800
#define NBLK_VIS  (BB * 4)               // 128
#define NBLK_WC   384                    // 384 * 384 f4 = H*H/4
#define NBLK_MEGA (NBLK_AGG + NBLK_VIS + NBLK_WC)   // 1312 (single wave)

// ---------------------------------------------------------------------------
// Scratch (device globals; allocation forbidden)
// ---------------------------------------------------------------------------
__device__ unsigned short g_af[BSROWS * HH];    // fp16 segment means (A)
__device__ unsigned short g_wf[HH * HH];        // fp16 W1 (w[:, :768])
__device__ float g_vispart[BB * 4 * HH];        // partial sums of vision rows

// ---------------------------------------------------------------------------
// Helpers
// ---------------------------------------------------------------------------
__device__ __forceinline__ uint32_t smem_u32(const void* p) {
    uint32_t a;
    asm("{ .reg .u64 t; cvta.to.shared.u64 t, %1; cvt.u32.u64 %0, t; }" : "=r"(a) : "l"(p));
    return a;
}
__device__ __forceinline__ void cpasync16(uint32_t saddr, const void* g) {
    asm volatile("cp.async.cg.shared.global [%0], [%1], 16;" :: "r"(saddr), "l"(g));
}
#define CP_COMMIT() asm volatile("cp.async.commit_group;" ::: "memory")

__device__ __forceinline__ void ldsm_x4(uint32_t* r, uint32_t addr) {
    asm volatile("ldmatrix.sync.aligned.m8n8.x4.shared.b16 {%0,%1,%2,%3}, [%4];"
                 : "=r"(r[0]), "=r"(r[1]), "=r"(r[2]), "=r"(r[3]) : "r"(addr));
}
__device__ __forceinline__ void ldsm_x2(uint32_t* r, uint32_t addr) {
    asm volatile("ldmatrix.sync.aligned.m8n8.x2.shared.b16 {%0,%1}, [%2];"
                 : "=r"(r[0]), "=r"(r[1]) : "r"(addr));
}
__device__ __forceinline__ void mma_f16(float* c, const uint32_t* a, const uint32_t* b) {
    asm volatile("mma.sync.aligned.m16n8k16.row.col.f32.f16.f16.f32 "
                 "{%0,%1,%2,%3}, {%4,%5,%6,%7}, {%8,%9}, {%0,%1,%2,%3};"
                 : "+f"(c[0]), "+f"(c[1]), "+f"(c[2]), "+f"(c[3])
                 : "r"(a[0]), "r"(a[1]), "r"(a[2]), "r"(a[3]), "r"(b[0]), "r"(b[1]));
}

// pack 4 floats -> 4 fp16 in a uint2
__device__ __forceinline__ uint2 pack4h(float4 v) {
    __half2 p01 = __floats2half2_rn(v.x, v.y);
    __half2 p23 = __floats2half2_rn(v.z, v.w);
    uint2 u;
    u.x = *reinterpret_cast<uint32_t*>(&p01);
    u.y = *reinterpret_cast<uint32_t*>(&p23);
    return u;
}

// accumulate a segment's rows (list in smem) into a float4 and store fp16 mean
__device__ __forceinline__ void seg_accum_store(const float* __restrict__ base,
                                                const unsigned short* __restrict__ list,
                                                int cnt, int h4, size_t orow) {
    float inv = (cnt > 0) ? (1.0f / (float)cnt) : 0.0f;
    float4 acc = make_float4(0.f, 0.f, 0.f, 0.f);
    int i = 0;
    for (; i + 8 <= cnt; i += 8) {
        float4 v[8];
        #pragma unroll
        for (int j = 0; j < 8; j++)
            v[j] = *(const float4*)&base[(size_t)list[i + j] * HH + h4 * 4];
        #pragma unroll
        for (int j = 0; j < 8; j++) {
            acc.x += v[j].x; acc.y += v[j].y; acc.z += v[j].z; acc.w += v[j].w;
        }
    }
    for (; i + 4 <= cnt; i += 4) {
        float4 v[4];
        #pragma unroll
        for (int j = 0; j < 4; j++)
            v[j] = *(const float4*)&base[(size_t)list[i + j] * HH + h4 * 4];
        #pragma unroll
        for (int j = 0; j < 4; j++) {
            acc.x += v[j].x; acc.y += v[j].y; acc.z += v[j].z; acc.w += v[j].w;
        }
    }
    for (; i < cnt; i++) {
        float4 v = *(const float4*)&base[(size_t)list[i] * HH + h4 * 4];
        acc.x += v.x; acc.y += v.y; acc.z += v.z; acc.w += v.w;
    }
    acc.x *= inv; acc.y *= inv; acc.z *= inv; acc.w *= inv;
    *(uint2*)&g_af[orow * HH + h4 * 4] = pack4h(acc);
}

// ---------------------------------------------------------------------------
// Mega kernel: block-range specialization fuses agg (4 segments per block) /
// vision partials / W1 fp16 convert so they overlap on-chip. 192 threads.
// Grid 1312 blocks <= single-wave capacity: everything resident at once.
// ---------------------------------------------------------------------------
__global__ __launch_bounds__(192) void mega_kernel(const float* __restrict__ feat,
                                                   const int* __restrict__ mask,
                                                   const float* __restrict__ w) {
    const int blk = blockIdx.x;

    if (blk < NBLK_AGG) {
        // ---- segment means -> fp16. One block per (b, segment-quad). ----
        int b = blk / (SS / 4);
        int s0 = (blk % (SS / 4)) * 4;          // segments s0..s0+3

        __shared__ unsigned short lists[4][TT];  // 16 KB
        __shared__ int cnts[4];
        if (threadIdx.x < 4) cnts[threadIdx.x] = 0;
        __syncthreads();

        const int* mrow = mask + (size_t)b * TT;
        for (int t = threadIdx.x; t < TT; t += 192) {
            int m = mrow[t] - 1 - s0;           // 0..3 if in this quad
            if ((unsigned)m < 4u) {
                int pos = atomicAdd(&cnts[m], 1);
                lists[m][pos] = (unsigned short)t;
            }
        }
        __syncthreads();

        const float* base = feat + ((size_t)b * ROWSTRIDE + NVV) * HH;
        int h4 = threadIdx.x;                   // 0..191
        size_t row0 = (size_t)b * SS + s0;
        #pragma unroll
        for (int q = 0; q < 4; q++)
            seg_accum_store(base, lists[q], cnts[q], h4, row0 + q);

    } else if (blk < NBLK_AGG + NBLK_VIS) {
        // ---- vision partial sums: 25 rows per block ----
        int idx = blk - NBLK_AGG;
        int b = idx >> 2, part = idx & 3;
        const float* base = feat + ((size_t)b * ROWSTRIDE + part * 25) * HH;
        int h4 = threadIdx.x;
        float4 acc = make_float4(0.f, 0.f, 0.f, 0.f);
        int r = 0;
        for (; r + 4 <= 25; r += 4) {
            float4 v0 = *(const float4*)&base[(size_t)(r + 0) * HH + h4 * 4];
            float4 v1 = *(const float4*)&base[(size_t)(r + 1) * HH + h4 * 4];
            float4 v2 = *(const float4*)&base[(size_t)(r + 2) * HH + h4 * 4];
            float4 v3 = *(const float4*)&base[(size_t)(r + 3) * HH + h4 * 4];
            acc.x += v0.x + v1.x + v2.x + v3.x;
            acc.y += v0.y + v1.y + v2.y + v3.y;
            acc.z += v0.z + v1.z + v2.z + v3.z;
            acc.w += v0.w + v1.w + v2.w + v3.w;
        }
        for (; r < 25; r++) {
            float4 v = *(const float4*)&base[(size_t)r * HH + h4 * 4];
            acc.x += v.x; acc.y += v.y; acc.z += v.z; acc.w += v.w;
        }
        *(float4*)&g_vispart[(size_t)idx * HH + h4 * 4] = acc;

    } else {
        // ---- W1 -> fp16: 384 float4s per block (2 per thread) ----
        int wblk = blk - (NBLK_AGG + NBLK_VIS);
        int i0 = wblk * 384 + threadIdx.x;
        #pragma unroll
        for (int j = 0; j < 2; j++) {
            int idx = i0 + j * 192;
            int n = idx / (HH / 4);
            int k4 = idx % (HH / 4);
            float4 v = *(const float4*)&w[(size_t)n * K2 + k4 * 4];
            *(uint2*)&g_wf[(size_t)n * HH + k4 * 4] = pack4h(v);
        }
    }
}

// ---------------------------------------------------------------------------
// Kernel: mma.sync fp16 GEMM (R14 config) with fused v2 prologue.
// out[m][n] = sum_k A[m][k]*W1[n][k] + v2[m/S][n]
// BM=160, BN=128, BK=32, 24 stages, 4 smem buffers, grid (6,20)=120 CTAs.
// 8 warps 2(m)x4(n); warp tile 80x32.
// Prologue: this CTA's <=3 batches x 128 n of v2 = vis_mean.W2^T + bias,
// computed in fp32 into a dedicated smem region (v2s) past the stage buffers.
// ---------------------------------------------------------------------------
#define BM 160
#define NSTG 24
#define NBUF 4
#define ROWH 40                       // padded row length in halfs (80 B)
#define STGA (BM * ROWH)              // A halfs per stage (6400)
#define STGB (128 * ROWH)             // B halfs per stage (5120)
#define STAGE_BYTES ((NBUF * STGA + NBUF * STGB) * 2)   // 92160
#define GEMM_SMEM (STAGE_BYTES + 3 * 128 * 4)           // + v2s = 93696 B

__global__ __launch_bounds__(256) void gemm_kernel(const float* __restrict__ w,
                                                   const float* __restrict__ bias,
                                                   float* __restrict__ out) {
    extern __shared__ unsigned short sm[];
    unsigned short* sA = sm;
    unsigned short* sB = sA + NBUF * STGA;
    float* v2s = (float*)((char*)sm + STAGE_BYTES);   // [3][128]

    const int tid = threadIdx.x;
    const int lane = tid & 31;
    const int wid = tid >> 5;
    const int wm = wid >> 2;          // 0..1 -> m offset wm*80
    const int wn = wid & 3;           // 0..3 -> n offset wn*32
    const int n0 = blockIdx.x * 128;
    const int m0 = blockIdx.y * BM;

    const uint32_t bA = smem_u32(sA), bB = smem_u32(sB);

    // ---- Prologue: fused v2 for this CTA's batches & n-range ----
    const int b_lo = m0 / SS;
    const int b_hi = (m0 + BM - 1) / SS;
    const int nb = b_hi - b_lo + 1;             // 2 or 3
    {
        float* sv = (float*)sm;                 // nb*768 floats (stage area, pre-pipeline)
        const float invN = 1.0f / (float)NVV;
        for (int i = tid; i < nb * HH; i += 256) {
            int bb = i / HH, h = i % HH;
            const float* pp = &g_vispart[(size_t)((b_lo + bb) * 4) * HH + h];
            sv[i] = (pp[0] + pp[HH] + pp[2 * HH] + pp[3 * HH]) * invN;
        }
        __syncthreads();

        // warp wid handles n = n0 + wid*16 + i, i in 0..15
        for (int i = 0; i < 16; i++) {
            int n = n0 + wid * 16 + i;
            const float* wr = w + (size_t)n * K2 + HH;     // W2 row n
            float a0 = 0.f, a1 = 0.f, a2 = 0.f;
            #pragma unroll
            for (int it = 0; it < 6; it++) {
                int k4 = it * 32 + lane;
                float4 wv = *(const float4*)&wr[k4 * 4];
                const float* s0 = &sv[k4 * 4];
                float4 x0 = *(const float4*)s0;
                a0 += x0.x * wv.x + x0.y * wv.y + x0.z * wv.z + x0.w * wv.w;
                if (nb > 1) {
                    float4 x1 = *(const float4*)(s0 + HH);
                    a1 += x1.x * wv.x + x1.y * wv.y + x1.z * wv.z + x1.w * wv.w;
                }
                if (nb > 2) {
                    float4 x2 = *(const float4*)(s0 + 2 * HH);
                    a2 += x2.x * wv.x + x2.y * wv.y + x2.z * wv.z + x2.w * wv.w;
                }
            }
            #pragma unroll
            for (int off = 16; off; off >>= 1) {
                a0 += __shfl_xor_sync(0xFFFFFFFFu, a0, off);
                a1 += __shfl_xor_sync(0xFFFFFFFFu, a1, off);
                a2 += __shfl_xor_sync(0xFFFFFFFFu, a2, off);
            }
            if (lane == 0) {
                float bb = bias[n];
                v2s[0 * 128 + (n - n0)] = a0 + bb;
                if (nb > 1) v2s[1 * 128 + (n - n0)] = a1 + bb;
                if (nb > 2) v2s[2 * 128 + (n - n0)] = a2 + bb;
            }
        }
        __syncthreads();   // sv consumed; stage area free for the pipeline
    }

    float acc[5][4][4];
    #pragma unroll
    for (int i = 0; i < 5; i++)
        #pragma unroll
        for (int j = 0; j < 4; j++)
            #pragma unroll
            for (int r = 0; r < 4; r++) acc[i][j][r] = 0.f;

    auto issue_stage = [&](int s, int buf) {
        const int k0 = s * 32;
        #pragma unroll
        for (int j = 0; j < 3; j++) {
            int idx = tid + j * 256;
            if (idx < BM * 4) {
                int row = idx >> 2;
                int c16 = idx & 3;
                int kk = k0 + c16 * 8;
                uint32_t soff = (uint32_t)(buf * STGA + row * ROWH + c16 * 8) * 2u;
                cpasync16(bA + soff, &g_af[(size_t)(m0 + row) * HH + kk]);
            }
        }
        #pragma unroll
        for (int j = 0; j < 2; j++) {
            int idx = tid + j * 256;
            int row = idx >> 2;
            int c16 = idx & 3;
            int kk = k0 + c16 * 8;
            uint32_t soff = (uint32_t)(buf * STGB + row * ROWH + c16 * 8) * 2u;
            cpasync16(bB + soff, &g_wf[(size_t)(n0 + row) * HH + kk]);
        }
        CP_COMMIT();
    };

    issue_stage(0, 0);
    issue_stage(1, 1);
    issue_stage(2, 2);

    for (int s = 0; s < NSTG; s++) {
        int rem = NSTG - 1 - s;
        if (rem >= 2)      asm volatile("cp.async.wait_group 2;" ::: "memory");
        else if (rem == 1) asm volatile("cp.async.wait_group 1;" ::: "memory");
        else               asm volatile("cp.async.wait_group 0;" ::: "memory");
        __syncthreads();

        if (s + 3 < NSTG) issue_stage(s + 3, (s + 3) % NBUF);

        const int buf = s % NBUF;
        const uint32_t stgA = (uint32_t)(buf * STGA) * 2u;
        const uint32_t stgB = (uint32_t)(buf * STGB) * 2u;

        #pragma unroll
        for (int ks = 0; ks < 2; ks++) {
            const int kh = ks * 16;
            uint32_t a[5][4], b[4][2];

            #pragma unroll
            for (int ti = 0; ti < 5; ti++) {
                int mr = wm * 80 + ti * 16 + (lane & 15);
                uint32_t off = stgA + (uint32_t)(mr * ROWH + kh + (lane >> 4) * 8) * 2u;
                ldsm_x4(a[ti], bA + off);
            }
            #pragma unroll
            for (int tj = 0; tj < 4; tj++) {
                int nr = wn * 32 + tj * 8 + (lane & 7);
                uint32_t off = stgB + (uint32_t)(nr * ROWH + kh + ((lane >> 3) & 1) * 8) * 2u;
                ldsm_x2(b[tj], bB + off);
            }

            #pragma unroll
            for (int ti = 0; ti < 5; ti++)
                #pragma unroll
                for (int tj = 0; tj < 4; tj++)
                    mma_f16(acc[ti][tj], a[ti], b[tj]);
        }
    }
    __syncthreads();   // all warps done before smem reuse

    // Epilogue: fragments -> padded fp32 smem tile -> coalesced store + v2 add.
    float* st = (float*)sm;                     // 160 x 129 floats = 82560 B (< STAGE_BYTES; v2s untouched)
    const int g = lane >> 2;
    const int t2 = (lane & 3) * 2;
    #pragma unroll
    for (int ti = 0; ti < 5; ti++)
        #pragma unroll
        for (int tj = 0; tj < 4; tj++) {
            int r0 = wm * 80 + ti * 16 + g;
            int c0 = wn * 32 + tj * 8 + t2;
            st[r0 * 129 + c0]           = acc[ti][tj][0];
            st[r0 * 129 + c0 + 1]       = acc[ti][tj][1];
            st[(r0 + 8) * 129 + c0]     = acc[ti][tj][2];
            st[(r0 + 8) * 129 + c0 + 1] = acc[ti][tj][3];
        }
    __syncthreads();

    #pragma unroll 4
    for (int it = 0; it < BM * 128 / 256; it++) {
        int q = tid + it * 256;
        int row = q >> 7;
        int col = q & 127;
        int m = m0 + row;
        int b = m / SS;
        out[(size_t)m * HH + n0 + col] = st[row * 129 + col] + v2s[(b - b_lo) * 128 + col];
    }
}

// ---------------------------------------------------------------------------
extern "C" void kernel_launch(void* const* d_in, const int* in_sizes, int n_in,
                              void* d_out, int out_size) {
    const float* feat = (const float*)d_in[0];   // (B, NV+T, H) f32
    const int*   mask = (const int*)d_in[1];     // (B, T) i32
    const float* w    = (const float*)d_in[2];   // (H, 2H) f32
    const float* bias = (const float*)d_in[3];   // (H,) f32
    float* out = (float*)d_out;                  // (B, S, H) f32

    mega_kernel<<<NBLK_MEGA, 192>>>(feat, mask, w);

    cudaFuncSetAttribute(gemm_kernel, cudaFuncAttributeMaxDynamicSharedMemorySize, GEMM_SMEM);
    gemm_kernel<<<dim3(HH / 128, BSROWS / BM), 256, GEMM_SMEM>>>(w, bias, out);
}

// round 17
// speedup vs baseline: 1.0691x; 1.0475x over previous
#include <cuda_runtime.h>
#include <cuda_fp16.h>
#include <stdint.h>

// Problem constants
#define BB 32
#define TT 2000
#define HH 768
#define SS 100
#define NVV 100
#define BSROWS 3200            // B*S
#define ROWSTRIDE 2100         // NV + T
#define K2 1536                // 2*H

// Block-range layout of mega_kernel (agg blocks handle FOUR segments each)
#define NBLK_AGG  (BSROWS / 4)           // 800
#define NBLK_VIS  (BB * 4)               // 128
#define NBLK_WC   384                    // 384 * 384 f4 = H*H/4
#define NBLK_MEGA (NBLK_AGG + NBLK_VIS + NBLK_WC)   // 1312 (single wave)

// ---------------------------------------------------------------------------
// Scratch (device globals; allocation forbidden)
// ---------------------------------------------------------------------------
__device__ unsigned short g_af[BSROWS * HH];    // fp16 segment means (A)
__device__ unsigned short g_wf[HH * HH];        // fp16 W1 (w[:, :768])
__device__ float g_vispart[BB * 4 * HH];        // partial sums of vision rows

// ---------------------------------------------------------------------------
// Helpers
// ---------------------------------------------------------------------------
__device__ __forceinline__ uint32_t smem_u32(const void* p) {
    uint32_t a;
    asm("{ .reg .u64 t; cvta.to.shared.u64 t, %1; cvt.u32.u64 %0, t; }" : "=r"(a) : "l"(p));
    return a;
}
__device__ __forceinline__ void cpasync16(uint32_t saddr, const void* g) {
    asm volatile("cp.async.cg.shared.global [%0], [%1], 16;" :: "r"(saddr), "l"(g));
}
#define CP_COMMIT() asm volatile("cp.async.commit_group;" ::: "memory")

__device__ __forceinline__ void ldsm_x4(uint32_t* r, uint32_t addr) {
    asm volatile("ldmatrix.sync.aligned.m8n8.x4.shared.b16 {%0,%1,%2,%3}, [%4];"
                 : "=r"(r[0]), "=r"(r[1]), "=r"(r[2]), "=r"(r[3]) : "r"(addr));
}
__device__ __forceinline__ void mma_f16(float* c, const uint32_t* a, const uint32_t* b) {
    asm volatile("mma.sync.aligned.m16n8k16.row.col.f32.f16.f16.f32 "
                 "{%0,%1,%2,%3}, {%4,%5,%6,%7}, {%8,%9}, {%0,%1,%2,%3};"
                 : "+f"(c[0]), "+f"(c[1]), "+f"(c[2]), "+f"(c[3])
                 : "r"(a[0]), "r"(a[1]), "r"(a[2]), "r"(a[3]), "r"(b[0]), "r"(b[1]));
}

// pack 4 floats -> 4 fp16 in a uint2
__device__ __forceinline__ uint2 pack4h(float4 v) {
    __half2 p01 = __floats2half2_rn(v.x, v.y);
    __half2 p23 = __floats2half2_rn(v.z, v.w);
    uint2 u;
    u.x = *reinterpret_cast<uint32_t*>(&p01);
    u.y = *reinterpret_cast<uint32_t*>(&p23);
    return u;
}

// accumulate a segment's rows (list in smem) into a float4 and store fp16 mean
__device__ __forceinline__ void seg_accum_store(const float* __restrict__ base,
                                                const unsigned short* __restrict__ list,
                                                int cnt, int h4, size_t orow) {
    float inv = (cnt > 0) ? (1.0f / (float)cnt) : 0.0f;
    float4 acc = make_float4(0.f, 0.f, 0.f, 0.f);
    int i = 0;
    for (; i + 8 <= cnt; i += 8) {
        float4 v[8];
        #pragma unroll
        for (int j = 0; j < 8; j++)
            v[j] = *(const float4*)&base[(size_t)list[i + j] * HH + h4 * 4];
        #pragma unroll
        for (int j = 0; j < 8; j++) {
            acc.x += v[j].x; acc.y += v[j].y; acc.z += v[j].z; acc.w += v[j].w;
        }
    }
    for (; i + 4 <= cnt; i += 4) {
        float4 v[4];
        #pragma unroll
        for (int j = 0; j < 4; j++)
            v[j] = *(const float4*)&base[(size_t)list[i + j] * HH + h4 * 4];
        #pragma unroll
        for (int j = 0; j < 4; j++) {
            acc.x += v[j].x; acc.y += v[j].y; acc.z += v[j].z; acc.w += v[j].w;
        }
    }
    for (; i < cnt; i++) {
        float4 v = *(const float4*)&base[(size_t)list[i] * HH + h4 * 4];
        acc.x += v.x; acc.y += v.y; acc.z += v.z; acc.w += v.w;
    }
    acc.x *= inv; acc.y *= inv; acc.z *= inv; acc.w *= inv;
    *(uint2*)&g_af[orow * HH + h4 * 4] = pack4h(acc);
}

// ---------------------------------------------------------------------------
// Mega kernel: block-range specialization fuses agg (4 segments per block) /
// vision partials / W1 fp16 convert so they overlap on-chip. 192 threads.
// Grid 1312 blocks <= single-wave capacity: everything resident at once.
// ---------------------------------------------------------------------------
__global__ __launch_bounds__(192) void mega_kernel(const float* __restrict__ feat,
                                                   const int* __restrict__ mask,
                                                   const float* __restrict__ w) {
    const int blk = blockIdx.x;

    if (blk < NBLK_AGG) {
        // ---- segment means -> fp16. One block per (b, segment-quad). ----
        int b = blk / (SS / 4);
        int s0 = (blk % (SS / 4)) * 4;          // segments s0..s0+3

        __shared__ unsigned short lists[4][TT];  // 16 KB
        __shared__ int cnts[4];
        if (threadIdx.x < 4) cnts[threadIdx.x] = 0;
        __syncthreads();

        const int* mrow = mask + (size_t)b * TT;
        for (int t = threadIdx.x; t < TT; t += 192) {
            int m = mrow[t] - 1 - s0;           // 0..3 if in this quad
            if ((unsigned)m < 4u) {
                int pos = atomicAdd(&cnts[m], 1);
                lists[m][pos] = (unsigned short)t;
            }
        }
        __syncthreads();

        const float* base = feat + ((size_t)b * ROWSTRIDE + NVV) * HH;
        int h4 = threadIdx.x;                   // 0..191
        size_t row0 = (size_t)b * SS + s0;
        #pragma unroll
        for (int q = 0; q < 4; q++)
            seg_accum_store(base, lists[q], cnts[q], h4, row0 + q);

    } else if (blk < NBLK_AGG + NBLK_VIS) {
        // ---- vision partial sums: 25 rows per block ----
        int idx = blk - NBLK_AGG;
        int b = idx >> 2, part = idx & 3;
        const float* base = feat + ((size_t)b * ROWSTRIDE + part * 25) * HH;
        int h4 = threadIdx.x;
        float4 acc = make_float4(0.f, 0.f, 0.f, 0.f);
        int r = 0;
        for (; r + 4 <= 25; r += 4) {
            float4 v0 = *(const float4*)&base[(size_t)(r + 0) * HH + h4 * 4];
            float4 v1 = *(const float4*)&base[(size_t)(r + 1) * HH + h4 * 4];
            float4 v2 = *(const float4*)&base[(size_t)(r + 2) * HH + h4 * 4];
            float4 v3 = *(const float4*)&base[(size_t)(r + 3) * HH + h4 * 4];
            acc.x += v0.x + v1.x + v2.x + v3.x;
            acc.y += v0.y + v1.y + v2.y + v3.y;
            acc.z += v0.z + v1.z + v2.z + v3.z;
            acc.w += v0.w + v1.w + v2.w + v3.w;
        }
        for (; r < 25; r++) {
            float4 v = *(const float4*)&base[(size_t)r * HH + h4 * 4];
            acc.x += v.x; acc.y += v.y; acc.z += v.z; acc.w += v.w;
        }
        *(float4*)&g_vispart[(size_t)idx * HH + h4 * 4] = acc;

    } else {
        // ---- W1 -> fp16: 384 float4s per block (2 per thread) ----
        int wblk = blk - (NBLK_AGG + NBLK_VIS);
        int i0 = wblk * 384 + threadIdx.x;
        #pragma unroll
        for (int j = 0; j < 2; j++) {
            int idx = i0 + j * 192;
            int n = idx / (HH / 4);
            int k4 = idx % (HH / 4);
            float4 v = *(const float4*)&w[(size_t)n * K2 + k4 * 4];
            *(uint2*)&g_wf[(size_t)n * HH + k4 * 4] = pack4h(v);
        }
    }
}

// ---------------------------------------------------------------------------
// Kernel: mma.sync fp16 GEMM with fused v2 prologue. BK=64, 12 stages,
// fragment double-buffering across k16-steps, paired B ldsm_x4.
// out[m][n] = sum_k A[m][k]*W1[n][k] + v2[m/S][n]
// BM=160, BN=128, BK=64, NBUF=4, grid (6,20)=120 CTAs (single wave).
// 8 warps 2(m)x4(n); warp tile 80x32.
// ---------------------------------------------------------------------------
#define BM 160
#define BK 64
#define NSTG 12
#define NBUF 4
#define ROWH 72                       // 64 halfs + 8 pad (144 B rows, conflict-free)
#define STGA (BM * ROWH)              // 11520 halfs
#define STGB (128 * ROWH)             // 9216 halfs
#define STAGE_BYTES ((NBUF * STGA + NBUF * STGB) * 2)   // 165888
#define GEMM_SMEM (STAGE_BYTES + 3 * 128 * 4)           // + v2s = 167424 B

__global__ __launch_bounds__(256) void gemm_kernel(const float* __restrict__ w,
                                                   const float* __restrict__ bias,
                                                   float* __restrict__ out) {
    extern __shared__ unsigned short sm[];
    unsigned short* sA = sm;
    unsigned short* sB = sA + NBUF * STGA;
    float* v2s = (float*)((char*)sm + STAGE_BYTES);   // [3][128]

    const int tid = threadIdx.x;
    const int lane = tid & 31;
    const int wid = tid >> 5;
    const int wm = wid >> 2;          // 0..1 -> m offset wm*80
    const int wn = wid & 3;           // 0..3 -> n offset wn*32
    const int n0 = blockIdx.x * 128;
    const int m0 = blockIdx.y * BM;

    const uint32_t bA = smem_u32(sA), bB = smem_u32(sB);

    // ---- Prologue: fused v2 for this CTA's batches & n-range ----
    const int b_lo = m0 / SS;
    const int b_hi = (m0 + BM - 1) / SS;
    const int nb = b_hi - b_lo + 1;             // 2 or 3
    {
        float* sv = (float*)sm;                 // nb*768 floats (stage area, pre-pipeline)
        const float invN = 1.0f / (float)NVV;
        for (int i = tid; i < nb * HH; i += 256) {
            int bb = i / HH, h = i % HH;
            const float* pp = &g_vispart[(size_t)((b_lo + bb) * 4) * HH + h];
            sv[i] = (pp[0] + pp[HH] + pp[2 * HH] + pp[3 * HH]) * invN;
        }
        __syncthreads();

        for (int i = 0; i < 16; i++) {
            int n = n0 + wid * 16 + i;
            const float* wr = w + (size_t)n * K2 + HH;     // W2 row n
            float a0 = 0.f, a1 = 0.f, a2 = 0.f;
            #pragma unroll
            for (int it = 0; it < 6; it++) {
                int k4 = it * 32 + lane;
                float4 wv = *(const float4*)&wr[k4 * 4];
                const float* s0 = &sv[k4 * 4];
                float4 x0 = *(const float4*)s0;
                a0 += x0.x * wv.x + x0.y * wv.y + x0.z * wv.z + x0.w * wv.w;
                if (nb > 1) {
                    float4 x1 = *(const float4*)(s0 + HH);
                    a1 += x1.x * wv.x + x1.y * wv.y + x1.z * wv.z + x1.w * wv.w;
                }
                if (nb > 2) {
                    float4 x2 = *(const float4*)(s0 + 2 * HH);
                    a2 += x2.x * wv.x + x2.y * wv.y + x2.z * wv.z + x2.w * wv.w;
                }
            }
            #pragma unroll
            for (int off = 16; off; off >>= 1) {
                a0 += __shfl_xor_sync(0xFFFFFFFFu, a0, off);
                a1 += __shfl_xor_sync(0xFFFFFFFFu, a1, off);
                a2 += __shfl_xor_sync(0xFFFFFFFFu, a2, off);
            }
            if (lane == 0) {
                float bb = bias[n];
                v2s[0 * 128 + (n - n0)] = a0 + bb;
                if (nb > 1) v2s[1 * 128 + (n - n0)] = a1 + bb;
                if (nb > 2) v2s[2 * 128 + (n - n0)] = a2 + bb;
            }
        }
        __syncthreads();   // sv consumed; stage area free for the pipeline
    }

    float acc[5][4][4];
    #pragma unroll
    for (int i = 0; i < 5; i++)
        #pragma unroll
        for (int j = 0; j < 4; j++)
            #pragma unroll
            for (int r = 0; r < 4; r++) acc[i][j][r] = 0.f;

    auto issue_stage = [&](int s, int buf) {
        const int k0 = s * BK;
        // A: 160 rows x 8 chunks = 1280; 5 per thread
        #pragma unroll
        for (int j = 0; j < 5; j++) {
            int idx = tid + j * 256;
            int row = idx >> 3;
            int c16 = idx & 7;
            uint32_t soff = (uint32_t)(buf * STGA + row * ROWH + c16 * 8) * 2u;
            cpasync16(bA + soff, &g_af[(size_t)(m0 + row) * HH + k0 + c16 * 8]);
        }
        // B: 128 rows x 8 chunks = 1024; 4 per thread
        #pragma unroll
        for (int j = 0; j < 4; j++) {
            int idx = tid + j * 256;
            int row = idx >> 3;
            int c16 = idx & 7;
            uint32_t soff = (uint32_t)(buf * STGB + row * ROWH + c16 * 8) * 2u;
            cpasync16(bB + soff, &g_wf[(size_t)(n0 + row) * HH + k0 + c16 * 8]);
        }
        CP_COMMIT();
    };

    issue_stage(0, 0);
    issue_stage(1, 1);
    issue_stage(2, 2);

    // fragment loader for k16-step kh within current stage buffers
    auto load_frags = [&](uint32_t stgA, uint32_t stgB, int kh,
                          uint32_t a[5][4], uint32_t b[4][2]) {
        #pragma unroll
        for (int ti = 0; ti < 5; ti++) {
            int mr = wm * 80 + ti * 16 + (lane & 15);
            uint32_t off = stgA + (uint32_t)(mr * ROWH + kh + (lane >> 4) * 8) * 2u;
            ldsm_x4(a[ti], bA + off);
        }
        // paired B: one ldsm_x4 covers tj pair {2p, 2p+1} x both k-halves
        #pragma unroll
        for (int p = 0; p < 2; p++) {
            int q = lane >> 3;                   // 0..3 matrix index
            int nr = wn * 32 + p * 16 + (q >> 1) * 8 + (lane & 7);
            int kc = kh + (q & 1) * 8;
            uint32_t off = stgB + (uint32_t)(nr * ROWH + kc) * 2u;
            uint32_t r[4];
            ldsm_x4(r, bB + off);
            b[2 * p][0] = r[0]; b[2 * p][1] = r[1];
            b[2 * p + 1][0] = r[2]; b[2 * p + 1][1] = r[3];
        }
    };

    for (int s = 0; s < NSTG; s++) {
        int rem = NSTG - 1 - s;
        if (rem >= 2)      asm volatile("cp.async.wait_group 2;" ::: "memory");
        else if (rem == 1) asm volatile("cp.async.wait_group 1;" ::: "memory");
        else               asm volatile("cp.async.wait_group 0;" ::: "memory");
        __syncthreads();

        if (s + 3 < NSTG) issue_stage(s + 3, (s + 3) % NBUF);

        const int buf = s % NBUF;
        const uint32_t stgA = (uint32_t)(buf * STGA) * 2u;
        const uint32_t stgB = (uint32_t)(buf * STGB) * 2u;

        uint32_t afr[2][5][4], bfr[2][4][2];
        load_frags(stgA, stgB, 0, afr[0], bfr[0]);

        #pragma unroll
        for (int ks = 0; ks < 4; ks++) {
            const int cur = ks & 1;
            if (ks < 3)
                load_frags(stgA, stgB, (ks + 1) * 16, afr[cur ^ 1], bfr[cur ^ 1]);

            #pragma unroll
            for (int ti = 0; ti < 5; ti++)
                #pragma unroll
                for (int tj = 0; tj < 4; tj++)
                    mma_f16(acc[ti][tj], afr[cur][ti], bfr[cur][tj]);
        }
    }
    __syncthreads();   // all warps done before smem reuse

    // Epilogue: fragments -> padded fp32 smem tile -> coalesced store + v2 add.
    float* st = (float*)sm;                     // 160 x 129 floats (< STAGE_BYTES; v2s untouched)
    const int g = lane >> 2;
    const int t2 = (lane & 3) * 2;
    #pragma unroll
    for (int ti = 0; ti < 5; ti++)
        #pragma unroll
        for (int tj = 0; tj < 4; tj++) {
            int r0 = wm * 80 + ti * 16 + g;
            int c0 = wn * 32 + tj * 8 + t2;
            st[r0 * 129 + c0]           = acc[ti][tj][0];
            st[r0 * 129 + c0 + 1]       = acc[ti][tj][1];
            st[(r0 + 8) * 129 + c0]     = acc[ti][tj][2];
            st[(r0 + 8) * 129 + c0 + 1] = acc[ti][tj][3];
        }
    __syncthreads();

    #pragma unroll 4
    for (int it = 0; it < BM * 128 / 256; it++) {
        int q = tid + it * 256;
        int row = q >> 7;
        int col = q & 127;
        int m = m0 + row;
        int b = m / SS;
        out[(size_t)m * HH + n0 + col] = st[row * 129 + col] + v2s[(b - b_lo) * 128 + col];
    }
}

// ---------------------------------------------------------------------------
extern "C" void kernel_launch(void* const* d_in, const int* in_sizes, int n_in,
                              void* d_out, int out_size) {
    const float* feat = (const float*)d_in[0];   // (B, NV+T, H) f32
    const int*   mask = (const int*)d_in[1];     // (B, T) i32
    const float* w    = (const float*)d_in[2];   // (H, 2H) f32
    const float* bias = (const float*)d_in[3];   // (H,) f32
    float* out = (float*)d_out;                  // (B, S, H) f32

    mega_kernel<<<NBLK_MEGA, 192>>>(feat, mask, w);

    cudaFuncSetAttribute(gemm_kernel, cudaFuncAttributeMaxDynamicSharedMemorySize, GEMM_SMEM);
    gemm_kernel<<<dim3(HH / 128, BSROWS / BM), 256, GEMM_SMEM>>>(w, bias, out);
}